// round 5
// baseline (speedup 1.0000x reference)
#include <cuda_runtime.h>
#include <cstdint>

// dims: B*P=8, T=32 -> TOK=256; NLAT=8, NSP=64 -> D=512; NE=100
#define TOK   256
#define NEX   100
#define NBP   8
#define NBIG  51200          // 8*64*100 columns of the big GEMM
#define NSTEPS 14            // Ann^(2^m) == 0 in fp32 beyond this

// ---------- static scratch (no allocation allowed) ----------
__device__ float g_Wt [512 * 1536];
__device__ float g_kqv[TOK * 1536];          // k | q | v per token
__device__ float g_tmp[(size_t)TOK * NBIG];  // 52.4 MB
__device__ float g_S  [TOK * NEX];
__device__ float g_M0 [NEX * NEX];
__device__ float g_M1 [NEX * NEX];
__device__ float g_u  [NBP * NEX];
__device__ float g_h  [(size_t)NBP * 512 * 512];

// ---------- packed f32x2 helpers (sm_103a; ptxas never emits FFMA2 on its own)
__device__ __forceinline__ unsigned long long bcast2(float a) {
    unsigned long long r;
    asm("mov.b64 %0, {%1, %1};" : "=l"(r) : "f"(a));
    return r;
}
__device__ __forceinline__ void fma2(unsigned long long& d,
                                     unsigned long long a,
                                     unsigned long long b) {
    asm("fma.rn.f32x2 %0, %1, %2, %0;" : "+l"(d) : "l"(a), "l"(b));
}

// ---------- K0: weight transpose  Wt[i=(c*64+x)][g*512+o=(C*64+X)] = W_g[X][C][x][c]
__global__ void transpose_weights(const float* __restrict__ Kw,
                                  const float* __restrict__ Qw,
                                  const float* __restrict__ Vw)
{
    int tid = blockIdx.x * blockDim.x + threadIdx.x;
    if (tid >= 3 * 262144) return;
    int g = tid >> 18, r = tid & 262143;
    int i = r >> 9, o = r & 511;
    int c = i >> 6, xs = i & 63, C = o >> 6, X = o & 63;
    const float* W = (g == 0) ? Kw : ((g == 1) ? Qw : Vw);
    g_Wt[i * 1536 + g * 512 + o] = W[((X * 8 + C) * 64 + xs) * 8 + c];
}

// ---------- tiled SGEMM, FFMA2 inner product. BMODE 0: B row-major [K][N].
// BMODE 1: B[i][j] = Ano[(i>>6)][j/6400][(i&63)][(j%6400)/100][j%100]
template<int BM, int BN, int BK, int TM, int TN, int BMODE>
__global__ __launch_bounds__((BM/TM)*(BN/TN))
void sgemm_kernel(const float* __restrict__ A, int lda,
                  const float* __restrict__ B, int ldb,
                  float* __restrict__ C, int ldc, int Kdim)
{
    constexpr int THREADS = (BM / TM) * (BN / TN);
    static_assert(TN % 2 == 0, "TN must be even for f32x2 pairing");
    __shared__ float As[BK][BM];
    __shared__ float Bs[BK][BN];
    const int tid = threadIdx.x;
    const int m0 = blockIdx.y * BM, n0 = blockIdx.x * BN;
    const int tx = tid % (BN / TN), ty = tid / (BN / TN);

    unsigned long long acc[TM][TN / 2];     // packed pairs along N
#pragma unroll
    for (int i = 0; i < TM; i++)
#pragma unroll
        for (int j = 0; j < TN / 2; j++) acc[i][j] = 0ull;

    constexpr int K4 = BK / 4;
    constexpr int A_LOADS = BM * K4 / THREADS;
    constexpr int AROWSTEP = THREADS / K4;
    const int ar = tid / K4, ac = (tid % K4) * 4;
    constexpr int N4 = BN / 4;
    constexpr int B_LOADS = BK * N4 / THREADS;
    constexpr int BROWSTEP = THREADS / N4;
    const int br = tid / N4, bc = (tid % N4) * 4;

    long colbase = 0;
    if (BMODE == 1) colbase = (long)(n0 / 6400) * 409600 + (n0 % 6400);

    for (int kk = 0; kk < Kdim; kk += BK) {
#pragma unroll
        for (int l = 0; l < A_LOADS; l++) {
            int r = ar + l * AROWSTEP;
            float4 v = *(const float4*)(A + (long)(m0 + r) * lda + kk + ac);
            As[ac + 0][r] = v.x; As[ac + 1][r] = v.y;
            As[ac + 2][r] = v.z; As[ac + 3][r] = v.w;
        }
#pragma unroll
        for (int l = 0; l < B_LOADS; l++) {
            int r = br + l * BROWSTEP;
            int i = kk + r;
            const float* src = (BMODE == 0)
                ? (B + (long)i * ldb + n0 + bc)
                : (B + (long)(i >> 6) * 3276800 + (long)(i & 63) * 6400 + colbase + bc);
            *(float4*)(&Bs[r][bc]) = *(const float4*)src;
        }
        __syncthreads();
#pragma unroll
        for (int k = 0; k < BK; k++) {
            unsigned long long af2[TM], bf2[TN / 2];
#pragma unroll
            for (int i = 0; i < TM; i++) af2[i] = bcast2(As[k][ty * TM + i]);
#pragma unroll
            for (int j = 0; j < TN / 2; j++)
                bf2[j] = *(const unsigned long long*)(&Bs[k][tx * TN + 2 * j]);
#pragma unroll
            for (int i = 0; i < TM; i++)
#pragma unroll
                for (int j = 0; j < TN / 2; j++) fma2(acc[i][j], af2[i], bf2[j]);
        }
        __syncthreads();
    }
#pragma unroll
    for (int i = 0; i < TM; i++) {
        int m = m0 + ty * TM + i;
#pragma unroll
        for (int j = 0; j < TN / 2; j++)
            *(unsigned long long*)(C + (long)m * ldc + n0 + tx * TN + 2 * j) = acc[i][j];
    }
}

// ---------- S[t][n] = sum_{ky} tmp[t][ky*100+n] * v[t][ky]
__global__ void s_reduce_kernel()
{
    int t = blockIdx.x;
    __shared__ float vs[512];
    for (int i = threadIdx.x; i < 512; i += blockDim.x)
        vs[i] = g_kqv[t * 1536 + 1024 + i];
    __syncthreads();
    int n = threadIdx.x;
    if (n < NEX) {
        const float* tp = g_tmp + (size_t)t * NBIG + n;
        float a0 = 0.f, a1 = 0.f, a2 = 0.f, a3 = 0.f;
        for (int ky = 0; ky < 512; ky += 4) {
            a0 += tp[(ky + 0) * 100] * vs[ky + 0];
            a1 += tp[(ky + 1) * 100] * vs[ky + 1];
            a2 += tp[(ky + 2) * 100] * vs[ky + 2];
            a3 += tp[(ky + 3) * 100] * vs[ky + 3];
        }
        g_S[t * NEX + n] = (a0 + a1) + (a2 + a3);
    }
}

// ---------- chain step: blocks 0..99 square Min; blocks 100..107 update u
__global__ void chain_step_kernel(const float* __restrict__ Min,
                                  float* __restrict__ Mout,
                                  int scol, int first)
{
    int b = blockIdx.x;
    if (b < 100) {
        __shared__ float arow[NEX];
        for (int i = threadIdx.x; i < NEX; i += blockDim.x) arow[i] = Min[b * NEX + i];
        __syncthreads();
        int j = threadIdx.x;
        if (j < NEX) {
            float acc = 0.f;
#pragma unroll 4
            for (int k = 0; k < NEX; k++) acc += arow[k] * Min[k * NEX + j];
            Mout[b * NEX + j] = acc;
        }
    } else {
        int bp = b - 100;
        __shared__ float sv[NEX];
        for (int i = threadIdx.x; i < NEX; i += blockDim.x)
            sv[i] = g_S[(bp * 32 + scol) * NEX + i];
        __syncthreads();
        int n = threadIdx.x;
        if (n < NEX) {
            float acc = 0.f;
#pragma unroll 4
            for (int m = 0; m < NEX; m++) acc += Min[n * NEX + m] * sv[m];
            float base = first ? g_S[(bp * 32 + 30) * NEX + n] : g_u[bp * NEX + n];
            g_u[bp * NEX + n] = base + acc;
        }
    }
}

// ---------- hmat[bp][o][j] = Aoo[o>>6,j>>6,o&63,j&63]*k_last[o]*v_last[j]
//                           + sum_n Aon[o>>6,j>>6,o&63,j&63,n]*u[bp][n]
__global__ void build_h_kernel(const float* __restrict__ Aoo,
                               const float* __restrict__ Aon)
{
    __shared__ __align__(16) float us[NBP * NEX];
    for (int i = threadIdx.x; i < NBP * NEX; i += blockDim.x) us[i] = g_u[i];
    __syncthreads();
    int tid = blockIdx.x * blockDim.x + threadIdx.x;   // 262144 total
    int o = tid >> 9, j = tid & 511;
    int c1 = o >> 6, x1 = o & 63, c2 = j >> 6, x2 = j & 63;
    size_t aidx = (size_t)(((c1 * 8 + c2) * 64 + x1) * 64 + x2);
    const float4* ap = (const float4*)(Aon + aidx * 100);
    const float4* up = (const float4*)us;

    float acc[NBP];
#pragma unroll
    for (int bp = 0; bp < NBP; bp++) acc[bp] = 0.f;
#pragma unroll 5
    for (int q4 = 0; q4 < 25; q4++) {
        float4 a = ap[q4];
#pragma unroll
        for (int bp = 0; bp < NBP; bp++) {
            float4 uu = up[bp * 25 + q4];
            acc[bp] += a.x * uu.x + a.y * uu.y + a.z * uu.z + a.w * uu.w;
        }
    }
    float aoo = Aoo[aidx];
#pragma unroll
    for (int bp = 0; bp < NBP; bp++) {
        float kl = g_kqv[(bp * 32 + 31) * 1536 + o];
        float vl = g_kqv[(bp * 32 + 31) * 1536 + 1024 + j];
        g_h[(size_t)bp * 262144 + tid] = aoo * kl * vl + acc[bp];
    }
}

// ---------- y[bp,t,j] = sum_o q[bp,t,o] * hmat[bp][o][j]
__global__ void final_gemm_kernel(float* __restrict__ y)
{
    int bp = blockIdx.y;
    int lane = threadIdx.x & 127, th = threadIdx.x >> 7;
    int j = blockIdx.x * 128 + lane;
    __shared__ float qs[32][33];   // [o_local][t]
    float acc[16];
#pragma unroll
    for (int tt = 0; tt < 16; tt++) acc[tt] = 0.f;

    for (int oc = 0; oc < 512; oc += 32) {
        __syncthreads();
        for (int l = threadIdx.x; l < 1024; l += 256) {
            int oo = l >> 5, t = l & 31;
            qs[oo][t] = g_kqv[(bp * 32 + t) * 1536 + 512 + oc + oo];
        }
        __syncthreads();
#pragma unroll 8
        for (int oo = 0; oo < 32; oo++) {
            float hv = g_h[(size_t)bp * 262144 + (size_t)(oc + oo) * 512 + j];
#pragma unroll
            for (int tt = 0; tt < 16; tt++)
                acc[tt] += qs[oo][th * 16 + tt] * hv;
        }
    }
#pragma unroll
    for (int tt = 0; tt < 16; tt++)
        y[(size_t)(bp * 32 + th * 16 + tt) * 512 + j] = acc[tt];
}

extern "C" void kernel_launch(void* const* d_in, const int* in_sizes, int n_in,
                              void* d_out, int out_size)
{
    const float* x   = (const float*)d_in[0];
    const float* Kw  = (const float*)d_in[1];
    const float* Qw  = (const float*)d_in[2];
    const float* Vw  = (const float*)d_in[3];
    const float* Aoo = (const float*)d_in[4];
    const float* Ann = (const float*)d_in[5];
    const float* Aon = (const float*)d_in[6];
    const float* Ano = (const float*)d_in[7];
    float* y = (float*)d_out;

    float *pWt, *pkqv, *ptmp, *pM0, *pM1;
    cudaGetSymbolAddress((void**)&pWt,  g_Wt);
    cudaGetSymbolAddress((void**)&pkqv, g_kqv);
    cudaGetSymbolAddress((void**)&ptmp, g_tmp);
    cudaGetSymbolAddress((void**)&pM0,  g_M0);
    cudaGetSymbolAddress((void**)&pM1,  g_M1);

    // 1. weight transpose
    transpose_weights<<<3072, 256>>>(Kw, Qw, Vw);

    // 2. kqv projection: [256x512] @ [512x1536]
    {
        dim3 grid(1536 / 64, TOK / 64);
        sgemm_kernel<64, 64, 16, 4, 4, 0><<<grid, 256>>>(x, 512, pWt, 1536, pkqv, 1536, 512);
    }

    // 3. big GEMM: tmp[t][j] = sum_i k[t][i] * AnoB[i][j]   [256x512]@[512x51200]
    {
        dim3 grid(NBIG / 128, TOK / 128);
        sgemm_kernel<128, 128, 32, 8, 8, 1><<<grid, 256>>>(pkqv, 1536, Ano, 0, ptmp, NBIG, 512);
    }

    // 4. S reduction
    s_reduce_kernel<<<TOK, 128>>>();

    // 5. Ann chain: u = S[30] + sum_j Ann^(2^j) @ S[29-j]
    {
        const float* Min = Ann;
        float* Mout = pM1;
        for (int j = 0; j < NSTEPS; j++) {
            chain_step_kernel<<<108, 128>>>(Min, Mout, 29 - j, j == 0);
            Min = Mout;
            Mout = (Mout == pM1) ? pM0 : pM1;
        }
    }

    // 6. h build
    build_h_kernel<<<1024, 256>>>(Aoo, Aon);

    // 7. final GEMM -> y
    {
        dim3 grid(4, NBP);
        final_gemm_kernel<<<grid, 256>>>(y);
    }
}

// round 6
// speedup vs baseline: 1.1923x; 1.1923x over previous
#include <cuda_runtime.h>
#include <cstdint>

// dims: B*P=8, T=32 -> TOK=256; NLAT=8, NSP=64 -> D=512; NE=100
#define TOK   256
#define NEX   100
#define NBP   8
#define NBIG  51200          // 8*64*100 columns of the big GEMM
#define NSTEPS 8             // Ann^(2^m): first dropped term ~rho^256 ~ 1e-77 -> 0

// ---------- static scratch (no allocation allowed) ----------
__device__ float g_Wt [512 * 1536];
__device__ float g_kqv[TOK * 1536];          // k | q | v per token
__device__ float g_tmp[(size_t)TOK * NBIG];  // 52.4 MB
__device__ float g_S  [TOK * NEX];
__device__ float g_M0 [NEX * NEX];
__device__ float g_M1 [NEX * NEX];
__device__ float g_u  [NBP * NEX];
__device__ float g_h  [(size_t)NBP * 512 * 512];

// ---------- packed f32x2 helpers (sm_103a; ptxas never emits FFMA2 on its own)
__device__ __forceinline__ unsigned long long bcast2(float a) {
    unsigned long long r;
    asm("mov.b64 %0, {%1, %1};" : "=l"(r) : "f"(a));
    return r;
}
__device__ __forceinline__ void fma2(unsigned long long& d,
                                     unsigned long long a,
                                     unsigned long long b) {
    asm("fma.rn.f32x2 %0, %1, %2, %0;" : "+l"(d) : "l"(a), "l"(b));
}

// ---------- K0: weight transpose  Wt[i=(c*64+x)][g*512+o=(C*64+X)] = W_g[X][C][x][c]
__global__ void transpose_weights(const float* __restrict__ Kw,
                                  const float* __restrict__ Qw,
                                  const float* __restrict__ Vw)
{
    int tid = blockIdx.x * blockDim.x + threadIdx.x;
    if (tid >= 3 * 262144) return;
    int g = tid >> 18, r = tid & 262143;
    int i = r >> 9, o = r & 511;
    int c = i >> 6, xs = i & 63, C = o >> 6, X = o & 63;
    const float* W = (g == 0) ? Kw : ((g == 1) ? Qw : Vw);
    g_Wt[i * 1536 + g * 512 + o] = W[((X * 8 + C) * 64 + xs) * 8 + c];
}

// ---------- tiled SGEMM, FFMA2 inner product, register-staged B prefetch.
// BMODE 0: B row-major [K][N].
// BMODE 1: B[i][j] = Ano[(i>>6)][j/6400][(i&63)][(j%6400)/100][j%100]
template<int BM, int BN, int BK, int TM, int TN, int BMODE>
__global__ __launch_bounds__((BM/TM)*(BN/TN))
void sgemm_kernel(const float* __restrict__ A, int lda,
                  const float* __restrict__ B, int ldb,
                  float* __restrict__ C, int ldc, int Kdim)
{
    constexpr int THREADS = (BM / TM) * (BN / TN);
    static_assert(TN % 2 == 0, "TN must be even for f32x2 pairing");
    __shared__ float As[BK][BM];
    __shared__ float Bs[BK][BN];
    const int tid = threadIdx.x;
    const int m0 = blockIdx.y * BM, n0 = blockIdx.x * BN;
    const int tx = tid % (BN / TN), ty = tid / (BN / TN);

    unsigned long long acc[TM][TN / 2];     // packed pairs along N
#pragma unroll
    for (int i = 0; i < TM; i++)
#pragma unroll
        for (int j = 0; j < TN / 2; j++) acc[i][j] = 0ull;

    constexpr int K4 = BK / 4;
    constexpr int A_LOADS = BM * K4 / THREADS;
    constexpr int AROWSTEP = THREADS / K4;
    const int ar = tid / K4, ac = (tid % K4) * 4;
    constexpr int N4 = BN / 4;
    constexpr int B_LOADS = BK * N4 / THREADS;
    constexpr int BROWSTEP = THREADS / N4;
    const int br = tid / N4, bc = (tid % N4) * 4;

    long colbase = 0;
    if (BMODE == 1) colbase = (long)(n0 / 6400) * 409600 + (n0 % 6400);

    // B global->reg prefetch buffer (B is the 105MB latency-critical stream;
    // A is a small L2-resident tile, loaded directly).
    float4 pb[B_LOADS];
#pragma unroll
    for (int l = 0; l < B_LOADS; l++) {
        int i = br + l * BROWSTEP;  // kk = 0
        const float* src = (BMODE == 0)
            ? (B + (long)i * ldb + n0 + bc)
            : (B + (long)(i >> 6) * 3276800 + (long)(i & 63) * 6400 + colbase + bc);
        pb[l] = *(const float4*)src;
    }

    for (int kk = 0; kk < Kdim; kk += BK) {
        // stage A directly, B from prefetch regs
#pragma unroll
        for (int l = 0; l < A_LOADS; l++) {
            int r = ar + l * AROWSTEP;
            float4 v = *(const float4*)(A + (long)(m0 + r) * lda + kk + ac);
            As[ac + 0][r] = v.x; As[ac + 1][r] = v.y;
            As[ac + 2][r] = v.z; As[ac + 3][r] = v.w;
        }
#pragma unroll
        for (int l = 0; l < B_LOADS; l++)
            *(float4*)(&Bs[br + l * BROWSTEP][bc]) = pb[l];
        __syncthreads();

        // prefetch next B tile while computing this one
        if (kk + BK < Kdim) {
#pragma unroll
            for (int l = 0; l < B_LOADS; l++) {
                int i = kk + BK + br + l * BROWSTEP;
                const float* src = (BMODE == 0)
                    ? (B + (long)i * ldb + n0 + bc)
                    : (B + (long)(i >> 6) * 3276800 + (long)(i & 63) * 6400 + colbase + bc);
                pb[l] = *(const float4*)src;
            }
        }

#pragma unroll
        for (int k = 0; k < BK; k++) {
            unsigned long long af2[TM], bf2[TN / 2];
#pragma unroll
            for (int i = 0; i < TM; i++) af2[i] = bcast2(As[k][ty * TM + i]);
#pragma unroll
            for (int j = 0; j < TN / 2; j++)
                bf2[j] = *(const unsigned long long*)(&Bs[k][tx * TN + 2 * j]);
#pragma unroll
            for (int i = 0; i < TM; i++)
#pragma unroll
                for (int j = 0; j < TN / 2; j++) fma2(acc[i][j], af2[i], bf2[j]);
        }
        __syncthreads();
    }
#pragma unroll
    for (int i = 0; i < TM; i++) {
        int m = m0 + ty * TM + i;
#pragma unroll
        for (int j = 0; j < TN / 2; j++)
            *(unsigned long long*)(C + (long)m * ldc + n0 + tx * TN + 2 * j) = acc[i][j];
    }
}

// ---------- S[t][n] = sum_{ky} tmp[t][ky*100+n] * v[t][ky]
// 512 threads: 4 ky-chunks x 128 n-lanes, smem tree reduce.
__global__ void s_reduce_kernel()
{
    int t = blockIdx.x;
    __shared__ float vs[512];
    __shared__ float red[512];
    int tid = threadIdx.x;                // 512
    vs[tid] = g_kqv[t * 1536 + 1024 + tid];
    __syncthreads();
    int c = tid >> 7, n = tid & 127;
    float a = 0.f;
    if (n < NEX) {
        const float* tp = g_tmp + (size_t)t * NBIG + n;
        int ky0 = c * 128;
        float a0 = 0.f, a1 = 0.f, a2 = 0.f, a3 = 0.f;
        for (int ky = ky0; ky < ky0 + 128; ky += 4) {
            a0 += tp[(ky + 0) * 100] * vs[ky + 0];
            a1 += tp[(ky + 1) * 100] * vs[ky + 1];
            a2 += tp[(ky + 2) * 100] * vs[ky + 2];
            a3 += tp[(ky + 3) * 100] * vs[ky + 3];
        }
        a = (a0 + a1) + (a2 + a3);
    }
    red[tid] = a;
    __syncthreads();
    if (tid < 128) {
        float s = (red[tid] + red[tid + 128]) + (red[tid + 256] + red[tid + 384]);
        if (tid < NEX) g_S[t * NEX + tid] = s;
    }
}

// ---------- chain step: blocks 0..99 square Min; blocks 100..107 update u
__global__ void chain_step_kernel(const float* __restrict__ Min,
                                  float* __restrict__ Mout,
                                  int scol, int first)
{
    int b = blockIdx.x;
    if (b < 100) {
        __shared__ float arow[NEX];
        for (int i = threadIdx.x; i < NEX; i += blockDim.x) arow[i] = Min[b * NEX + i];
        __syncthreads();
        int j = threadIdx.x;
        if (j < NEX) {
            float acc = 0.f;
#pragma unroll 4
            for (int k = 0; k < NEX; k++) acc += arow[k] * Min[k * NEX + j];
            Mout[b * NEX + j] = acc;
        }
    } else {
        int bp = b - 100;
        __shared__ float sv[NEX];
        for (int i = threadIdx.x; i < NEX; i += blockDim.x)
            sv[i] = g_S[(bp * 32 + scol) * NEX + i];
        __syncthreads();
        int n = threadIdx.x;
        if (n < NEX) {
            float acc = 0.f;
#pragma unroll 4
            for (int m = 0; m < NEX; m++) acc += Min[n * NEX + m] * sv[m];
            float base = first ? g_S[(bp * 32 + 30) * NEX + n] : g_u[bp * NEX + n];
            g_u[bp * NEX + n] = base + acc;
        }
    }
}

// ---------- hmat[bp][o][j] = Aoo[o>>6,j>>6,o&63,j&63]*k_last[o]*v_last[j]
//                           + sum_n Aon[o>>6,j>>6,o&63,j&63,n]*u[bp][n]
__global__ void build_h_kernel(const float* __restrict__ Aoo,
                               const float* __restrict__ Aon)
{
    __shared__ __align__(16) float us[NBP * NEX];
    for (int i = threadIdx.x; i < NBP * NEX; i += blockDim.x) us[i] = g_u[i];
    __syncthreads();
    int tid = blockIdx.x * blockDim.x + threadIdx.x;   // 262144 total
    int o = tid >> 9, j = tid & 511;
    int c1 = o >> 6, x1 = o & 63, c2 = j >> 6, x2 = j & 63;
    size_t aidx = (size_t)(((c1 * 8 + c2) * 64 + x1) * 64 + x2);
    const float4* ap = (const float4*)(Aon + aidx * 100);
    const float4* up = (const float4*)us;

    float acc[NBP];
#pragma unroll
    for (int bp = 0; bp < NBP; bp++) acc[bp] = 0.f;
#pragma unroll 5
    for (int q4 = 0; q4 < 25; q4++) {
        float4 a = ap[q4];
#pragma unroll
        for (int bp = 0; bp < NBP; bp++) {
            float4 uu = up[bp * 25 + q4];
            acc[bp] += a.x * uu.x + a.y * uu.y + a.z * uu.z + a.w * uu.w;
        }
    }
    float aoo = Aoo[aidx];
#pragma unroll
    for (int bp = 0; bp < NBP; bp++) {
        float kl = g_kqv[(bp * 32 + 31) * 1536 + o];
        float vl = g_kqv[(bp * 32 + 31) * 1536 + 1024 + j];
        g_h[(size_t)bp * 262144 + tid] = aoo * kl * vl + acc[bp];
    }
}

// ---------- y[bp,t,j] = sum_o q[bp,t,o] * hmat[bp][o][j]
__global__ void final_gemm_kernel(float* __restrict__ y)
{
    int bp = blockIdx.y;
    int lane = threadIdx.x & 127, th = threadIdx.x >> 7;
    int j = blockIdx.x * 128 + lane;
    __shared__ float qs[32][33];   // [o_local][t]
    float acc[16];
#pragma unroll
    for (int tt = 0; tt < 16; tt++) acc[tt] = 0.f;

    for (int oc = 0; oc < 512; oc += 32) {
        __syncthreads();
        for (int l = threadIdx.x; l < 1024; l += 256) {
            int oo = l >> 5, t = l & 31;
            qs[oo][t] = g_kqv[(bp * 32 + t) * 1536 + 512 + oc + oo];
        }
        __syncthreads();
#pragma unroll 8
        for (int oo = 0; oo < 32; oo++) {
            float hv = g_h[(size_t)bp * 262144 + (size_t)(oc + oo) * 512 + j];
#pragma unroll
            for (int tt = 0; tt < 16; tt++)
                acc[tt] += qs[oo][th * 16 + tt] * hv;
        }
    }
#pragma unroll
    for (int tt = 0; tt < 16; tt++)
        y[(size_t)(bp * 32 + th * 16 + tt) * 512 + j] = acc[tt];
}

extern "C" void kernel_launch(void* const* d_in, const int* in_sizes, int n_in,
                              void* d_out, int out_size)
{
    const float* x   = (const float*)d_in[0];
    const float* Kw  = (const float*)d_in[1];
    const float* Qw  = (const float*)d_in[2];
    const float* Vw  = (const float*)d_in[3];
    const float* Aoo = (const float*)d_in[4];
    const float* Ann = (const float*)d_in[5];
    const float* Aon = (const float*)d_in[6];
    const float* Ano = (const float*)d_in[7];
    float* y = (float*)d_out;

    float *pWt, *pkqv, *ptmp, *pM0, *pM1;
    cudaGetSymbolAddress((void**)&pWt,  g_Wt);
    cudaGetSymbolAddress((void**)&pkqv, g_kqv);
    cudaGetSymbolAddress((void**)&ptmp, g_tmp);
    cudaGetSymbolAddress((void**)&pM0,  g_M0);
    cudaGetSymbolAddress((void**)&pM1,  g_M1);

    // 1. weight transpose
    transpose_weights<<<3072, 256>>>(Kw, Qw, Vw);

    // 2. kqv projection: [256x512] @ [512x1536]
    {
        dim3 grid(1536 / 64, TOK / 64);
        sgemm_kernel<64, 64, 16, 4, 4, 0><<<grid, 256>>>(x, 512, pWt, 1536, pkqv, 1536, 512);
    }

    // 3. big GEMM: tmp[t][j] = sum_i k[t][i] * AnoB[i][j]   [256x512]@[512x51200]
    {
        dim3 grid(NBIG / 128, TOK / 128);
        sgemm_kernel<128, 128, 32, 8, 8, 1><<<grid, 256>>>(pkqv, 1536, Ano, 0, ptmp, NBIG, 512);
    }

    // 4. S reduction
    s_reduce_kernel<<<TOK, 512>>>();

    // 5. Ann chain: u = S[30] + sum_j Ann^(2^j) @ S[29-j]
    {
        const float* Min = Ann;
        float* Mout = pM1;
        for (int j = 0; j < NSTEPS; j++) {
            chain_step_kernel<<<108, 128>>>(Min, Mout, 29 - j, j == 0);
            Min = Mout;
            Mout = (Mout == pM1) ? pM0 : pM1;
        }
    }

    // 6. h build
    build_h_kernel<<<1024, 256>>>(Aoo, Aon);

    // 7. final GEMM -> y
    {
        dim3 grid(4, NBP);
        final_gemm_kernel<<<grid, 256>>>(y);
    }
}